// round 6
// baseline (speedup 1.0000x reference)
#include <cuda_runtime.h>

// ---- Problem constants -----------------------------------------------------
#define CC   128
#define HH   112
#define WW   112
#define HO   56
#define WO   56
#define P_TOT  12845056   // B*C*HO*WO (output elements)

// ---- Accurate logf (njuffa, max err 0.85089 ulp), fast-math-proof ----------
__device__ __forceinline__ float log_acc(float a) {
    int   e = (__float_as_int(a) - 0x3f2aaaab) & 0xff800000;
    float m = __int_as_float(__float_as_int(a) - e);
    float i = (float)e * 1.19209290e-7f;     // 2^-23
    m = m - 1.0f;
    float s = m * m;
    float r = -0.130310059f;
    float t =  0.140869141f;
    r = fmaf(r, s, -0.121483512f);
    t = fmaf(t, s,  0.139814854f);
    r = fmaf(r, s, -0.166846126f);
    t = fmaf(t, s,  0.200120345f);
    r = fmaf(r, s, -0.249996200f);
    r = fmaf(t, m, r);
    r = fmaf(r, m,  0.333331972f);
    r = fmaf(r, m, -0.500000000f);
    r = fmaf(r, s, m);
    r = fmaf(i, 0.693147182f, r);
    return r;
}

// bits -> uniform (JAX semantics) -> standard gumbel
__device__ __forceinline__ float gumbel_from_bits(unsigned bits) {
    float f = __uint_as_float((bits >> 9) | 0x3f800000u) - 1.0f;  // [0,1)
    float u = fmaxf(f + 1e-20f, 1e-20f);                          // JAX uniform(1e-20,1)
    return -log_acc(-log_acc(u));
}

// ---- Threefry-2x32, key (0,42), partitionable mode -------------------------
// counter = (hi=0, lo=i); returns xor-fold of the two output words.
#define TF_RND(r) { x0 += x1; x1 = __funnelshift_l(x1, x1, (r)); x1 ^= x0; }

__device__ __forceinline__ unsigned threefry_bits(unsigned lo) {
    const unsigned ks0 = 0u, ks1 = 42u, ks2 = 0x1BD11BDAu ^ 42u;
    unsigned x0 = ks0;           // hi counter word is 0 for N < 2^32
    unsigned x1 = lo + ks1;
    TF_RND(13) TF_RND(15) TF_RND(26) TF_RND(6)
    x0 += ks1; x1 += ks2 + 1u;
    TF_RND(17) TF_RND(29) TF_RND(16) TF_RND(24)
    x0 += ks2; x1 += ks0 + 2u;
    TF_RND(13) TF_RND(15) TF_RND(26) TF_RND(6)
    x0 += ks0; x1 += ks1 + 3u;
    TF_RND(17) TF_RND(29) TF_RND(16) TF_RND(24)
    x0 += ks1; x1 += ks2 + 4u;
    TF_RND(13) TF_RND(15) TF_RND(26) TF_RND(6)
    x0 += ks2; x1 += ks0 + 5u;
    return x0 ^ x1;              // 32-bit xor-fold (partitionable path)
}

// ---- Kernel: one thread per output patch -----------------------------------
__global__ __launch_bounds__(256)
void tdgs_pool_kernel(const float* __restrict__ x,
                      const float* __restrict__ temperature,
                      float* __restrict__ out) {
    unsigned p = blockIdx.x * blockDim.x + threadIdx.x;
    if (p >= P_TOT) return;

    unsigned wo  = p % WO;
    unsigned tmp = p / WO;
    unsigned ho  = tmp % HO;
    tmp         /= HO;
    unsigned c   = tmp % CC;
    unsigned b   = tmp / CC;

    float tp = temperature[(c * HO + ho) * WO + wo];
    tp = fmaxf(tp, 0.0f) + 0.1f;

    unsigned base = ((b * CC + c) * HH + 2u * ho) * WW + 2u * wo;
    float2 a0 = *reinterpret_cast<const float2*>(x + base);
    float2 a1 = *reinterpret_cast<const float2*>(x + base + WW);
    float xs[4] = {a0.x, a0.y, a1.x, a1.y};

    unsigned ctr = 4u * p;
    float best = -__int_as_float(0x7f800000);  // -inf
    float sel  = 0.0f;

    #pragma unroll
    for (int j = 0; j < 4; j++) {
        float g = gumbel_from_bits(threefry_bits(ctr + (unsigned)j));
        float v = __fdiv_rn(xs[j], tp) + g;
        if (v > best) { best = v; sel = xs[j]; }  // first-max wins ties
    }

    out[p] = sel;
}

extern "C" void kernel_launch(void* const* d_in, const int* in_sizes, int n_in,
                              void* d_out, int out_size) {
    const float* x    = (const float*)d_in[0];  // (32,128,112,112) f32
    const float* temp = (const float*)d_in[1];  // (128,56,56) f32
    float* out        = (float*)d_out;          // (32,128,56,56) f32
    (void)in_sizes; (void)n_in; (void)out_size;

    const int threads = 256;
    const int blocks  = (P_TOT + threads - 1) / threads;  // 50176
    tdgs_pool_kernel<<<blocks, threads>>>(x, temp, out);
}